// round 8
// baseline (speedup 1.0000x reference)
#include <cuda_runtime.h>

// ---------------- problem constants ----------------
#define N_NODES 100000
#define NE      1600000
#define NE3     4800000

// per-node precomputed A = Wfc1[:, :128] @ mvc_norm, B = Wfc1[:, 128:] @ mvc_norm + b_fc1
__device__ __align__(16) float g_A[(size_t)N_NODES * 64];
__device__ __align__(16) float g_B[(size_t)N_NODES * 64];

#define BN  64      // nodes per block
#define TPB 512
#define KC  32      // k-chunk for weight staging

// ---- shared memory layout (floats) ----
// xs : [256][68] X tile; overwritten by h tile after GEMM1; by ws3 [128][132] after GEMM2
// mvs: [128][68] mvc tile
// ws : 2 x [32][257] double-buffered staged weights
constexpr int XS_OFF  = 0;
constexpr int XS_SZ   = 256 * 68;            // 17408 (>= 128*132 = 16896 for ws3)
constexpr int MV_OFF  = XS_OFF + XS_SZ;
constexpr int MV_SZ   = 128 * 68;            // 8704
constexpr int WS_OFF  = MV_OFF + MV_SZ;
constexpr int WS_BUF  = 32 * 257;            // 8224
constexpr int WS_SZ   = 2 * WS_BUF;          // 16448
constexpr int RED_OFF = WS_OFF + WS_SZ;
constexpr int RED_SZ  = 8 * 64 + 64;
constexpr int SMEM_FLOATS = RED_OFF + RED_SZ;
constexpr int SMEM_BYTES  = SMEM_FLOATS * 4; // ~172.5 KB -> 1 block/SM

// ---------------- packed fp32x2 helpers (sm_103a) ----------------
__device__ __forceinline__ unsigned long long pack2(float v) {
    unsigned long long r;
    asm("mov.b64 %0, {%1, %1};" : "=l"(r) : "f"(v));
    return r;
}
__device__ __forceinline__ void ffma2(unsigned long long& d,
                                      unsigned long long a,
                                      unsigned long long b) {
    asm("fma.rn.f32x2 %0, %1, %2, %0;" : "+l"(d) : "l"(a), "l"(b));
}
__device__ __forceinline__ float2 unpack2(unsigned long long v) {
    float2 f;
    asm("mov.b64 {%0, %1}, %2;" : "=f"(f.x), "=f"(f.y) : "l"(v));
    return f;
}

// =====================================================================
// Node kernel: 64-node tile, fused, f32x2 FMAs.
// Double-buffered weight staging: while chunk c computes from buf[c&1],
// chunk c+1 (register-prefetched) is STS'd into buf[(c+1)&1] and chunk
// c+2's LDGs issue. One barrier per chunk.
// =====================================================================
__global__ void __launch_bounds__(TPB, 1) node_kernel(
    const float* __restrict__ trace,   // (2, N, 128)
    const float* __restrict__ Wlin,    // (256, 256)
    const float* __restrict__ Wlin2,   // (128, 256)
    const float* __restrict__ Wfc1,    // (64, 256)
    const float* __restrict__ bfc1)    // (64,)
{
    extern __shared__ float sm[];
    float* xs  = sm + XS_OFF;    // [k][68] X; later h [c][68]; later ws3 [k][132]
    float* mvs = sm + MV_OFF;    // [c][68]
    float* wsf = sm + WS_OFF;    // 2 x [kk][257]
    float* red = sm + RED_OFF;   // [8][64]
    float* nrm = red + 512;      // [64]

    const int t    = threadIdx.x;
    const int lane = t & 31;
    const int w    = t >> 5;     // 0..15
    const int n0   = blockIdx.x * BN;

    // ---- issue X tile loads into registers (coalesced along k) ----
    float xv[32];
    #pragma unroll
    for (int i = 0; i < 4; i++) {
        int nl = w * 4 + i;
        int n  = n0 + nl;
        #pragma unroll
        for (int j = 0; j < 8; j++) {
            int k = lane + 32 * j;
            float v = 0.0f;
            if (n < N_NODES) {
                v = (k < 128) ? trace[(size_t)n * 128 + k]
                              : trace[(size_t)(N_NODES + n) * 128 + (k - 128)];
            }
            xv[i * 8 + j] = v;
        }
    }
    // ---- prefetch GEMM1 weight chunk 0 into registers ----
    float wr[16];
    #pragma unroll
    for (int r = 0; r < 16; r++)
        wr[r] = Wlin[(w + 16 * r) * 256 + lane];

    // ---- store X tile to smem ----
    #pragma unroll
    for (int i = 0; i < 4; i++) {
        int nl = w * 4 + i;
        #pragma unroll
        for (int j = 0; j < 8; j++) {
            int k = lane + 32 * j;
            xs[k * 68 + nl] = xv[i * 8 + j];
        }
    }
    // ---- stage chunk 0 into buffer 0 ----
    #pragma unroll
    for (int r = 0; r < 16; r++)
        wsf[lane * 257 + (w + 16 * r)] = wr[r];
    __syncthreads();
    // ---- prefetch chunk 1 ----
    #pragma unroll
    for (int r = 0; r < 16; r++)
        wr[r] = Wlin[(w + 16 * r) * 256 + KC + lane];

    // ================= GEMM1: h = relu(Wlin @ x) =================
    const int c0 = t & 127;
    const int nn = (t >> 7) * 16;     // 16 nodes per quarter
    {
        unsigned long long a0[8], a1[8];
        #pragma unroll
        for (int i = 0; i < 8; i++) { a0[i] = 0ull; a1[i] = 0ull; }

        for (int c = 0; c < 8; c++) {
            float* buf  = wsf + (c & 1) * WS_BUF;
            float* nbuf = wsf + ((c + 1) & 1) * WS_BUF;
            // stage chunk c+1 into the other buffer (no one reads it now)
            if (c < 7) {
                #pragma unroll
                for (int r = 0; r < 16; r++)
                    nbuf[lane * 257 + (w + 16 * r)] = wr[r];
                if (c < 6) {
                    #pragma unroll
                    for (int r = 0; r < 16; r++)
                        wr[r] = Wlin[(w + 16 * r) * 256 + (c + 2) * KC + lane];
                } else {
                    // c == 6: prefetch GEMM2 chunk 0 instead
                    #pragma unroll
                    for (int r = 0; r < 8; r++)
                        wr[r] = Wlin2[(w + 16 * r) * 256 + lane];
                }
            }
            // compute chunk c
            #pragma unroll
            for (int kk = 0; kk < KC; kk++) {
                unsigned long long wv0 = pack2(buf[kk * 257 + c0]);
                unsigned long long wv1 = pack2(buf[kk * 257 + c0 + 128]);
                const ulonglong2* xr =
                    (const ulonglong2*)(xs + (c * KC + kk) * 68 + nn);
                #pragma unroll
                for (int q = 0; q < 4; q++) {
                    ulonglong2 x2 = xr[q];
                    ffma2(a0[2*q],   wv0, x2.x);
                    ffma2(a0[2*q+1], wv0, x2.y);
                    ffma2(a1[2*q],   wv1, x2.x);
                    ffma2(a1[2*q+1], wv1, x2.y);
                }
            }
            __syncthreads();
        }

        // ---- all xs reads done: store h (relu) into xs region [c][68] ----
        float4* h0 = (float4*)(xs + c0 * 68 + nn);
        float4* h1 = (float4*)(xs + (c0 + 128) * 68 + nn);
        #pragma unroll
        for (int q = 0; q < 4; q++) {
            float2 p = unpack2(a0[2*q]), r2 = unpack2(a0[2*q+1]);
            float4 v;
            v.x = fmaxf(p.x, 0.f);  v.y = fmaxf(p.y, 0.f);
            v.z = fmaxf(r2.x, 0.f); v.w = fmaxf(r2.y, 0.f);
            h0[q] = v;
            p = unpack2(a1[2*q]); r2 = unpack2(a1[2*q+1]);
            v.x = fmaxf(p.x, 0.f);  v.y = fmaxf(p.y, 0.f);
            v.z = fmaxf(r2.x, 0.f); v.w = fmaxf(r2.y, 0.f);
            h1[q] = v;
        }
    }

    // ---- stage GEMM2 chunk 0 (in wr since GEMM1 c==6) into buffer 0 ----
    #pragma unroll
    for (int r = 0; r < 8; r++)
        wsf[lane * 257 + (w + 16 * r)] = wr[r];
    __syncthreads();   // publishes h stores AND GEMM2 chunk 0
    #pragma unroll
    for (int r = 0; r < 8; r++)
        wr[r] = Wlin2[(w + 16 * r) * 256 + KC + lane];   // chunk 1 prefetch

    // ================= GEMM2: mvc = Wlin2 @ h =================
    const int d0 = t & 63;
    const int on = (t >> 6) * 8;      // 8 nodes per eighth
    {
        unsigned long long a0[4], a1[4];
        #pragma unroll
        for (int i = 0; i < 4; i++) { a0[i] = 0ull; a1[i] = 0ull; }

        for (int c = 0; c < 8; c++) {
            float* buf  = wsf + (c & 1) * WS_BUF;
            float* nbuf = wsf + ((c + 1) & 1) * WS_BUF;
            if (c < 7) {
                #pragma unroll
                for (int r = 0; r < 8; r++)
                    nbuf[lane * 257 + (w + 16 * r)] = wr[r];
                if (c < 6) {
                    #pragma unroll
                    for (int r = 0; r < 8; r++)
                        wr[r] = Wlin2[(w + 16 * r) * 256 + (c + 2) * KC + lane];
                }
            }
            #pragma unroll
            for (int kk = 0; kk < KC; kk++) {
                unsigned long long wv0 = pack2(buf[kk * 257 + d0]);
                unsigned long long wv1 = pack2(buf[kk * 257 + d0 + 64]);
                const ulonglong2* hr =
                    (const ulonglong2*)(xs + (c * KC + kk) * 68 + on);
                #pragma unroll
                for (int q = 0; q < 2; q++) {
                    ulonglong2 h2 = hr[q];
                    ffma2(a0[2*q],   wv0, h2.x);
                    ffma2(a0[2*q+1], wv0, h2.y);
                    ffma2(a1[2*q],   wv1, h2.x);
                    ffma2(a1[2*q+1], wv1, h2.y);
                }
            }
            __syncthreads();
        }
        // store mvc (disjoint region)
        float4* m0 = (float4*)(mvs + d0 * 68 + on);
        float4* m1 = (float4*)(mvs + (d0 + 64) * 68 + on);
        #pragma unroll
        for (int q = 0; q < 2; q++) {
            float2 p = unpack2(a0[2*q]), r2 = unpack2(a0[2*q+1]);
            m0[q] = make_float4(p.x, p.y, r2.x, r2.y);
            p = unpack2(a1[2*q]); r2 = unpack2(a1[2*q+1]);
            m1[q] = make_float4(p.x, p.y, r2.x, r2.y);
        }
    }
    __syncthreads();   // mvs stores visible

    // ---- issue GEMM3 weight loads (hidden under the norm phase) ----
    float wv3[32];
    #pragma unroll
    for (int r = 0; r < 8; r++) {
        int j  = w + 16 * r;
        int jj = j & 63;
        int koff = (j >= 64) ? 128 : 0;
        #pragma unroll
        for (int q = 0; q < 4; q++)
            wv3[r * 4 + q] = Wfc1[jj * 256 + koff + lane + 32 * q];
    }
    const float bias = __ldg(&bfc1[t & 63]);

    // ---------------- row norm + normalize ----------------
    {
        int n = t & 63, p = t >> 6;   // 8 groups x 16 cols
        float s = 0.0f;
        #pragma unroll 4
        for (int cc = p * 16; cc < p * 16 + 16; cc++) {
            float v = mvs[cc * 68 + n];
            s += v * v;
        }
        red[p * 64 + n] = s;
        __syncthreads();
        if (t < 64) {
            float ss = 0.0f;
            #pragma unroll
            for (int p2 = 0; p2 < 8; p2++) ss += red[p2 * 64 + t];
            nrm[t] = fmaxf(sqrtf(ss), 1e-12f);
        }
        __syncthreads();
        #pragma unroll
        for (int i = 0; i < 16; i++) {
            int idx = i * TPB + t;
            int cc = idx >> 6, n2 = idx & 63;
            mvs[cc * 68 + n2] = mvs[cc * 68 + n2] / nrm[n2];
        }
    }

    // ---- store GEMM3 weights into xs region (h dead after GEMM2) ----
    float* ws3 = xs;  // [k][132]
    #pragma unroll
    for (int r = 0; r < 8; r++) {
        int j = w + 16 * r;
        #pragma unroll
        for (int q = 0; q < 4; q++)
            ws3[(lane + 32 * q) * 132 + j] = wv3[r * 4 + q];
    }
    __syncthreads();   // publishes ws3 AND normalized mvs

    // ================= GEMM3: A/B = Wfc1-split @ mvc_norm =================
    {
        const int j0 = t & 63;
        unsigned long long aA[4], aB[4];
        #pragma unroll
        for (int i = 0; i < 4; i++) { aA[i] = 0ull; aB[i] = 0ull; }

        #pragma unroll 4
        for (int k = 0; k < 128; k++) {
            unsigned long long wv0 = pack2(ws3[k * 132 + j0]);
            unsigned long long wv1 = pack2(ws3[k * 132 + j0 + 64]);
            const ulonglong2* mr = (const ulonglong2*)(mvs + k * 68 + on);
            #pragma unroll
            for (int q = 0; q < 2; q++) {
                ulonglong2 m2 = mr[q];
                ffma2(aA[2*q],   wv0, m2.x);
                ffma2(aA[2*q+1], wv0, m2.y);
                ffma2(aB[2*q],   wv1, m2.x);
                ffma2(aB[2*q+1], wv1, m2.y);
            }
        }
        // store A, B (+bias fold into B), guard tail block
        #pragma unroll
        for (int q = 0; q < 4; q++) {
            float2 pa  = unpack2(aA[q]);
            float2 pb2 = unpack2(aB[q]);
            int n = n0 + on + 2 * q;
            if (n < N_NODES) {
                g_A[(size_t)n * 64 + j0] = pa.x;
                g_B[(size_t)n * 64 + j0] = pb2.x + bias;
            }
            if (n + 1 < N_NODES) {
                g_A[(size_t)(n + 1) * 64 + j0] = pa.y;
                g_B[(size_t)(n + 1) * 64 + j0] = pb2.y + bias;
            }
        }
    }
}

// =====================================================================
// Edge kernel: 8 threads/edge, difference-weight trick (R7, ~61us, at
// its L2 roofline for random 512B/edge gathers).
// =====================================================================
#define EPB 256
__global__ void __launch_bounds__(256) edge_kernel(
    const int*   __restrict__ ei,      // (2, 3*NE)
    const float* __restrict__ gum,     // (NE, 2)
    const float* __restrict__ Wfc2,    // (2, 64)
    const float* __restrict__ bfc2,    // (2,)
    float*       __restrict__ out)     // (3*NE,)
{
    __shared__ float sact[EPB];
    const int t  = threadIdx.x;
    const int g  = t & 7;
    const int gi = t >> 3;

    float wd[8];
    #pragma unroll
    for (int u = 0; u < 4; u++) {
        wd[u]     = Wfc2[g * 4 + u]      - Wfc2[64 + g * 4 + u];
        wd[4 + u] = Wfc2[32 + g * 4 + u] - Wfc2[96 + g * 4 + u];
    }
    const float cdiff = bfc2[0] - bfc2[1];
    const size_t e0 = (size_t)blockIdx.x * EPB;

    #pragma unroll
    for (int it = 0; it < EPB / 32; it++) {
        int    el = it * 32 + gi;
        size_t e  = e0 + el;

        int src = ei[e];
        int dst = ei[NE3 + e];
        const float4* ap = (const float4*)(g_A + (size_t)src * 64);
        const float4* bp = (const float4*)(g_B + (size_t)dst * 64);
        float4 a0 = ap[g], a1 = ap[8 + g];
        float4 b0 = bp[g], b1 = bp[8 + g];

        float sd = 0.0f, r;
        r = fmaxf(a0.x + b0.x, 0.f); sd = fmaf(wd[0], r, sd);
        r = fmaxf(a0.y + b0.y, 0.f); sd = fmaf(wd[1], r, sd);
        r = fmaxf(a0.z + b0.z, 0.f); sd = fmaf(wd[2], r, sd);
        r = fmaxf(a0.w + b0.w, 0.f); sd = fmaf(wd[3], r, sd);
        r = fmaxf(a1.x + b1.x, 0.f); sd = fmaf(wd[4], r, sd);
        r = fmaxf(a1.y + b1.y, 0.f); sd = fmaf(wd[5], r, sd);
        r = fmaxf(a1.z + b1.z, 0.f); sd = fmaf(wd[6], r, sd);
        r = fmaxf(a1.w + b1.w, 0.f); sd = fmaf(wd[7], r, sd);

        #pragma unroll
        for (int m = 1; m < 8; m <<= 1)
            sd += __shfl_xor_sync(0xffffffff, sd, m);

        if (g == 0) {
            float2 gm = ((const float2*)gum)[e];
            sact[el] = (sd + cdiff + gm.x - gm.y >= 0.0f) ? 1.0f : 0.0f;
        }
    }
    __syncthreads();

    float a = sact[t];
    out[e0 + t]          = a;
    out[NE + e0 + t]     = 1.0f - a;
    out[2 * NE + e0 + t] = 1.0f - a;
}

// =====================================================================
extern "C" void kernel_launch(void* const* d_in, const int* in_sizes, int n_in,
                              void* d_out, int out_size)
{
    const float* trace = (const float*)d_in[0];  // (2,100000,128)
    const float* Wlin  = (const float*)d_in[1];  // (256,256)
    const float* Wlin2 = (const float*)d_in[2];  // (128,256)
    const float* Wfc1  = (const float*)d_in[3];  // (64,256)
    const float* bfc1  = (const float*)d_in[4];  // (64,)
    const float* Wfc2  = (const float*)d_in[5];  // (2,64)
    const float* bfc2  = (const float*)d_in[6];  // (2,)
    const float* gum   = (const float*)d_in[7];  // (NE,2)
    const int*   ei    = (const int*)d_in[8];    // (2,3*NE)

    cudaFuncSetAttribute(node_kernel,
                         cudaFuncAttributeMaxDynamicSharedMemorySize, SMEM_BYTES);

    int nblocks = (N_NODES + BN - 1) / BN;   // 1563
    node_kernel<<<nblocks, TPB, SMEM_BYTES>>>(trace, Wlin, Wlin2, Wfc1, bfc1);

    int eblocks = NE / EPB;                  // 6250
    edge_kernel<<<eblocks, 256>>>(ei, gum, Wfc2, bfc2, (float*)d_out);
}

// round 12
// speedup vs baseline: 1.0830x; 1.0830x over previous
#include <cuda_runtime.h>

// ---------------- problem constants ----------------
#define N_NODES 100000
#define NE      1600000
#define NE3     4800000

// per-node precomputed A = Wfc1[:, :128] @ mvc_norm, B = Wfc1[:, 128:] @ mvc_norm + b_fc1
__device__ __align__(16) float g_A[(size_t)N_NODES * 64];
__device__ __align__(16) float g_B[(size_t)N_NODES * 64];

#define BN  32      // nodes per block (100000 = 3125 * 32, exact)
#define TPB 256
#define KC  32      // k-chunk for weight staging

// ---- shared memory layout (floats) ----
// xs : [256][36] X tile; overwritten by h tile after GEMM1
// mvs: [128][36] mvc tile
// ws : [32][257] staged weight chunk (GEMM1/2/3 all stream through here)
constexpr int XS_OFF  = 0;
constexpr int XS_SZ   = 256 * 36;            // 9216
constexpr int MV_OFF  = XS_OFF + XS_SZ;
constexpr int MV_SZ   = 128 * 36;            // 4608
constexpr int WS_OFF  = MV_OFF + MV_SZ;
constexpr int WS_SZ   = 32 * 257;            // 8224
constexpr int RED_OFF = WS_OFF + WS_SZ;
constexpr int RED_SZ  = 8 * 32 + 32;         // 288
constexpr int SMEM_FLOATS = RED_OFF + RED_SZ;
constexpr int SMEM_BYTES  = SMEM_FLOATS * 4; // 89344 B -> 2 blocks/SM

// ---------------- packed fp32x2 helpers (sm_103a) ----------------
__device__ __forceinline__ unsigned long long pack2(float v) {
    unsigned long long r;
    asm("mov.b64 %0, {%1, %1};" : "=l"(r) : "f"(v));
    return r;
}
__device__ __forceinline__ void ffma2(unsigned long long& d,
                                      unsigned long long a,
                                      unsigned long long b) {
    asm("fma.rn.f32x2 %0, %1, %2, %0;" : "+l"(d) : "l"(a), "l"(b));
}
__device__ __forceinline__ float2 unpack2(unsigned long long v) {
    float2 f;
    asm("mov.b64 {%0, %1}, %2;" : "=f"(f.x), "=f"(f.y) : "l"(v));
    return f;
}

// =====================================================================
// Node kernel: 32-node tile, 256 threads, 2 blocks/SM.
// R7-style register-prefetch staging: STS chunk c; bar; LDG chunk c+1;
// compute chunk c; bar. Two co-resident blocks overlap each other's
// stalls.
// =====================================================================
__global__ void __launch_bounds__(TPB, 2) node_kernel(
    const float* __restrict__ trace,   // (2, N, 128)
    const float* __restrict__ Wlin,    // (256, 256)
    const float* __restrict__ Wlin2,   // (128, 256)
    const float* __restrict__ Wfc1,    // (64, 256)
    const float* __restrict__ bfc1)    // (64,)
{
    extern __shared__ float sm[];
    float* xs  = sm + XS_OFF;    // [k][36] X; later h [c][36]
    float* mvs = sm + MV_OFF;    // [c][36]
    float* ws  = sm + WS_OFF;    // [kk][257]
    float* red = sm + RED_OFF;   // [8][32]
    float* nrm = red + 256;      // [32]

    const int t    = threadIdx.x;
    const int lane = t & 31;
    const int w    = t >> 5;     // 0..7
    const int n0   = blockIdx.x * BN;

    // ---- issue X tile loads into registers (coalesced along k) ----
    float xv[32];
    #pragma unroll
    for (int i = 0; i < 4; i++) {
        int nl = w * 4 + i;
        int n  = n0 + nl;
        #pragma unroll
        for (int j = 0; j < 8; j++) {
            int k = lane + 32 * j;
            xv[i * 8 + j] = (k < 128)
                ? trace[(size_t)n * 128 + k]
                : trace[(size_t)(N_NODES + n) * 128 + (k - 128)];
        }
    }
    // ---- prefetch GEMM1 weight chunk 0 into registers (32/thread) ----
    float wr[32];
    #pragma unroll
    for (int r = 0; r < 32; r++)
        wr[r] = Wlin[(w + 8 * r) * 256 + lane];

    // ---- store X tile to smem ----
    #pragma unroll
    for (int i = 0; i < 4; i++) {
        int nl = w * 4 + i;
        #pragma unroll
        for (int j = 0; j < 8; j++) {
            int k = lane + 32 * j;
            xs[k * 36 + nl] = xv[i * 8 + j];
        }
    }

    // ================= GEMM1: h = relu(Wlin @ x) =================
    // thread: cols {c0, c0+128}, 16 nodes (half)
    const int c0 = t & 127;
    const int nn = (t >> 7) * 16;
    {
        unsigned long long a0[8], a1[8];
        #pragma unroll
        for (int i = 0; i < 8; i++) { a0[i] = 0ull; a1[i] = 0ull; }

        for (int c = 0; c < 8; c++) {
            // publish chunk c weights (ws[kk][col], kk = lane)
            #pragma unroll
            for (int r = 0; r < 32; r++)
                ws[lane * 257 + (w + 8 * r)] = wr[r];
            __syncthreads();   // c==0: also publishes X tile
            // issue LDGs for chunk c+1 (hidden under compute)
            if (c < 7) {
                #pragma unroll
                for (int r = 0; r < 32; r++)
                    wr[r] = Wlin[(w + 8 * r) * 256 + (c + 1) * KC + lane];
            }
            // compute chunk c
            #pragma unroll
            for (int kk = 0; kk < KC; kk++) {
                unsigned long long wv0 = pack2(ws[kk * 257 + c0]);
                unsigned long long wv1 = pack2(ws[kk * 257 + c0 + 128]);
                const ulonglong2* xr =
                    (const ulonglong2*)(xs + (c * KC + kk) * 36 + nn);
                #pragma unroll
                for (int q = 0; q < 4; q++) {
                    ulonglong2 x2 = xr[q];
                    ffma2(a0[2*q],   wv0, x2.x);
                    ffma2(a0[2*q+1], wv0, x2.y);
                    ffma2(a1[2*q],   wv1, x2.x);
                    ffma2(a1[2*q+1], wv1, x2.y);
                }
            }
            __syncthreads();
        }

        // prefetch GEMM2 chunk 0 (16/thread) while storing h
        #pragma unroll
        for (int r = 0; r < 16; r++)
            wr[r] = Wlin2[(w + 8 * r) * 256 + lane];

        // store h (relu) into xs region, layout [c][36]
        float4* h0 = (float4*)(xs + c0 * 36 + nn);
        float4* h1 = (float4*)(xs + (c0 + 128) * 36 + nn);
        #pragma unroll
        for (int q = 0; q < 4; q++) {
            float2 p = unpack2(a0[2*q]), r2 = unpack2(a0[2*q+1]);
            float4 v;
            v.x = fmaxf(p.x, 0.f);  v.y = fmaxf(p.y, 0.f);
            v.z = fmaxf(r2.x, 0.f); v.w = fmaxf(r2.y, 0.f);
            h0[q] = v;
            p = unpack2(a1[2*q]); r2 = unpack2(a1[2*q+1]);
            v.x = fmaxf(p.x, 0.f);  v.y = fmaxf(p.y, 0.f);
            v.z = fmaxf(r2.x, 0.f); v.w = fmaxf(r2.y, 0.f);
            h1[q] = v;
        }
    }

    // ================= GEMM2: mvc = Wlin2 @ h =================
    // thread: cols {d0, d0+64}, 8 nodes (quarter)
    const int d0 = t & 63;
    const int on = (t >> 6) * 8;
    {
        unsigned long long b0[4], b1[4];
        #pragma unroll
        for (int i = 0; i < 4; i++) { b0[i] = 0ull; b1[i] = 0ull; }

        for (int c = 0; c < 8; c++) {
            #pragma unroll
            for (int r = 0; r < 16; r++)
                ws[lane * 257 + (w + 8 * r)] = wr[r];
            __syncthreads();   // c==0: also publishes h stores
            if (c < 7) {
                #pragma unroll
                for (int r = 0; r < 16; r++)
                    wr[r] = Wlin2[(w + 8 * r) * 256 + (c + 1) * KC + lane];
            }
            #pragma unroll
            for (int kk = 0; kk < KC; kk++) {
                unsigned long long wv0 = pack2(ws[kk * 257 + d0]);
                unsigned long long wv1 = pack2(ws[kk * 257 + d0 + 64]);
                const ulonglong2* hr =
                    (const ulonglong2*)(xs + (c * KC + kk) * 36 + on);
                #pragma unroll
                for (int q = 0; q < 2; q++) {
                    ulonglong2 h2 = hr[q];
                    ffma2(b0[2*q],   wv0, h2.x);
                    ffma2(b0[2*q+1], wv0, h2.y);
                    ffma2(b1[2*q],   wv1, h2.x);
                    ffma2(b1[2*q+1], wv1, h2.y);
                }
            }
            __syncthreads();
        }

        // prefetch GEMM3 chunk 0 (combined [A;B] rows) while storing mvc
        #pragma unroll
        for (int r = 0; r < 16; r++) {
            int j = w + 8 * r;
            wr[r] = (j < 64) ? Wfc1[j * 256 + lane]
                             : Wfc1[(j - 64) * 256 + 128 + lane];
        }

        // store mvc (disjoint region)
        float4* m0 = (float4*)(mvs + d0 * 36 + on);
        float4* m1 = (float4*)(mvs + (d0 + 64) * 36 + on);
        #pragma unroll
        for (int q = 0; q < 2; q++) {
            float2 p = unpack2(b0[2*q]), r2 = unpack2(b0[2*q+1]);
            m0[q] = make_float4(p.x, p.y, r2.x, r2.y);
            p = unpack2(b1[2*q]); r2 = unpack2(b1[2*q+1]);
            m1[q] = make_float4(p.x, p.y, r2.x, r2.y);
        }
    }
    __syncthreads();   // mvs stores visible

    const float bias = __ldg(&bfc1[t & 63]);

    // ---------------- row norm + normalize ----------------
    {
        int n = t & 31, p = t >> 5;   // 8 groups x 16 cols
        float s = 0.0f;
        #pragma unroll 4
        for (int cc = p * 16; cc < p * 16 + 16; cc++) {
            float v = mvs[cc * 36 + n];
            s += v * v;
        }
        red[p * 32 + n] = s;
        __syncthreads();
        if (t < 32) {
            float ss = 0.0f;
            #pragma unroll
            for (int p2 = 0; p2 < 8; p2++) ss += red[p2 * 32 + t];
            nrm[t] = fmaxf(sqrtf(ss), 1e-12f);
        }
        __syncthreads();
        #pragma unroll
        for (int i = 0; i < 16; i++) {
            int idx = i * TPB + t;
            int cc = idx >> 5, n2 = idx & 31;
            mvs[cc * 36 + n2] = mvs[cc * 36 + n2] / nrm[n2];
        }
    }

    // ================= GEMM3: A/B = Wfc1-split @ mvc_norm =================
    // 4 chunks of 32 k, streamed through ws like GEMM1/2.
    {
        const int j0 = t & 63;
        unsigned long long aA[4], aB[4];
        #pragma unroll
        for (int i = 0; i < 4; i++) { aA[i] = 0ull; aB[i] = 0ull; }

        for (int c = 0; c < 4; c++) {
            #pragma unroll
            for (int r = 0; r < 16; r++)
                ws[lane * 257 + (w + 8 * r)] = wr[r];
            __syncthreads();   // c==0: also publishes normalized mvs
            if (c < 3) {
                #pragma unroll
                for (int r = 0; r < 16; r++) {
                    int j = w + 8 * r;
                    wr[r] = (j < 64)
                        ? Wfc1[j * 256 + (c + 1) * KC + lane]
                        : Wfc1[(j - 64) * 256 + 128 + (c + 1) * KC + lane];
                }
            }
            #pragma unroll
            for (int kk = 0; kk < KC; kk++) {
                unsigned long long wv0 = pack2(ws[kk * 257 + j0]);
                unsigned long long wv1 = pack2(ws[kk * 257 + j0 + 64]);
                const ulonglong2* mr =
                    (const ulonglong2*)(mvs + (c * KC + kk) * 36 + on);
                #pragma unroll
                for (int q = 0; q < 2; q++) {
                    ulonglong2 m2 = mr[q];
                    ffma2(aA[2*q],   wv0, m2.x);
                    ffma2(aA[2*q+1], wv0, m2.y);
                    ffma2(aB[2*q],   wv1, m2.x);
                    ffma2(aB[2*q+1], wv1, m2.y);
                }
            }
            __syncthreads();
        }

        // store A, B (+bias fold into B); exact tiling, no bounds checks
        #pragma unroll
        for (int q = 0; q < 4; q++) {
            float2 pa  = unpack2(aA[q]);
            float2 pb2 = unpack2(aB[q]);
            int n = n0 + on + 2 * q;
            g_A[(size_t)n * 64 + j0]       = pa.x;
            g_A[(size_t)(n + 1) * 64 + j0] = pa.y;
            g_B[(size_t)n * 64 + j0]       = pb2.x + bias;
            g_B[(size_t)(n + 1) * 64 + j0] = pb2.y + bias;
        }
    }
}

// =====================================================================
// Edge kernel: 8 threads/edge, difference-weight trick (R7, ~61us, at
// its random-gather L2/issue roofline).
// =====================================================================
#define EPB 256
__global__ void __launch_bounds__(256) edge_kernel(
    const int*   __restrict__ ei,      // (2, 3*NE)
    const float* __restrict__ gum,     // (NE, 2)
    const float* __restrict__ Wfc2,    // (2, 64)
    const float* __restrict__ bfc2,    // (2,)
    float*       __restrict__ out)     // (3*NE,)
{
    __shared__ float sact[EPB];
    const int t  = threadIdx.x;
    const int g  = t & 7;
    const int gi = t >> 3;

    float wd[8];
    #pragma unroll
    for (int u = 0; u < 4; u++) {
        wd[u]     = Wfc2[g * 4 + u]      - Wfc2[64 + g * 4 + u];
        wd[4 + u] = Wfc2[32 + g * 4 + u] - Wfc2[96 + g * 4 + u];
    }
    const float cdiff = bfc2[0] - bfc2[1];
    const size_t e0 = (size_t)blockIdx.x * EPB;

    #pragma unroll
    for (int it = 0; it < EPB / 32; it++) {
        int    el = it * 32 + gi;
        size_t e  = e0 + el;

        int src = ei[e];
        int dst = ei[NE3 + e];
        const float4* ap = (const float4*)(g_A + (size_t)src * 64);
        const float4* bp = (const float4*)(g_B + (size_t)dst * 64);
        float4 a0 = ap[g], a1 = ap[8 + g];
        float4 b0 = bp[g], b1 = bp[8 + g];

        float sd = 0.0f, r;
        r = fmaxf(a0.x + b0.x, 0.f); sd = fmaf(wd[0], r, sd);
        r = fmaxf(a0.y + b0.y, 0.f); sd = fmaf(wd[1], r, sd);
        r = fmaxf(a0.z + b0.z, 0.f); sd = fmaf(wd[2], r, sd);
        r = fmaxf(a0.w + b0.w, 0.f); sd = fmaf(wd[3], r, sd);
        r = fmaxf(a1.x + b1.x, 0.f); sd = fmaf(wd[4], r, sd);
        r = fmaxf(a1.y + b1.y, 0.f); sd = fmaf(wd[5], r, sd);
        r = fmaxf(a1.z + b1.z, 0.f); sd = fmaf(wd[6], r, sd);
        r = fmaxf(a1.w + b1.w, 0.f); sd = fmaf(wd[7], r, sd);

        #pragma unroll
        for (int m = 1; m < 8; m <<= 1)
            sd += __shfl_xor_sync(0xffffffff, sd, m);

        if (g == 0) {
            float2 gm = ((const float2*)gum)[e];
            sact[el] = (sd + cdiff + gm.x - gm.y >= 0.0f) ? 1.0f : 0.0f;
        }
    }
    __syncthreads();

    float a = sact[t];
    out[e0 + t]          = a;
    out[NE + e0 + t]     = 1.0f - a;
    out[2 * NE + e0 + t] = 1.0f - a;
}

// =====================================================================
extern "C" void kernel_launch(void* const* d_in, const int* in_sizes, int n_in,
                              void* d_out, int out_size)
{
    const float* trace = (const float*)d_in[0];  // (2,100000,128)
    const float* Wlin  = (const float*)d_in[1];  // (256,256)
    const float* Wlin2 = (const float*)d_in[2];  // (128,256)
    const float* Wfc1  = (const float*)d_in[3];  // (64,256)
    const float* bfc1  = (const float*)d_in[4];  // (64,)
    const float* Wfc2  = (const float*)d_in[5];  // (2,64)
    const float* bfc2  = (const float*)d_in[6];  // (2,)
    const float* gum   = (const float*)d_in[7];  // (NE,2)
    const int*   ei    = (const int*)d_in[8];    // (2,3*NE)

    cudaFuncSetAttribute(node_kernel,
                         cudaFuncAttributeMaxDynamicSharedMemorySize, SMEM_BYTES);

    int nblocks = N_NODES / BN;              // 3125 exact
    node_kernel<<<nblocks, TPB, SMEM_BYTES>>>(trace, Wlin, Wlin2, Wfc1, bfc1);

    int eblocks = NE / EPB;                  // 6250
    edge_kernel<<<eblocks, 256>>>(ei, gum, Wfc2, bfc2, (float*)d_out);
}